// round 15
// baseline (speedup 1.0000x reference)
#include <cuda_runtime.h>
#include <cuda_bf16.h>
#include <cstdint>

// Problem constants (fixed by the dataset)
#define Tn 2000
#define Bn 64
#define Vn 163
#define Ln 200
#define Sn 401          // 2*L+1 extended states
#define NEGF (-1e30f)
#define CHK 14          // states per lane (even => j parity == state parity)
#define NOD 7           // odd (label) states per lane
#define DP  16          // prefetch depth (steps)
#define KMIN (-(1 << 29))
#define ROWSTRIDE (Bn * 32)   // uint4 elements per time row

// Packed per-(t,b) row: one uint4 (8 bf16) per lane: (r0,r1)(r2,r3)(r4,r5)(r6,0)
// r_i = exp(logit[label_i] - logit[blank]); +32 pad rows => no prefetch clamp
__device__ uint4  g_upk[(Tn + 32) * Bn * 32];   // ~66.6 MB
__device__ float  g_lse[Bn * Tn];      // adj = lse - logit_blank, [b][t] layout
__device__ double g_loss_total;        // accumulated by alpha blocks (zero-init)
__device__ int    g_done;              // completion counter (zero-init)

__device__ __forceinline__ uint32_t packbf(float a, float bx) {
    __nv_bfloat162 h = __floats2bfloat162_rn(a, bx);   // x=a(lo), y=bx(hi)
    return *reinterpret_cast<uint32_t*>(&h);
}

// ---------------------------------------------------------------------------
// Kernel 1: one warp per (t,b) row (skipped when t >= act[b] — never consumed).
// Raw logits -> warp smem; computes its own gather indices from labels;
// emits bf16-packed r slots and g_lse[b][t] = lse - logit_blank.
// ---------------------------------------------------------------------------
__global__ __launch_bounds__(256) void prep_kernel(const float* __restrict__ logits,
                                                   const int* __restrict__ act_lens,
                                                   const int* __restrict__ labels,
                                                   const int* __restrict__ label_lens) {
    __shared__ float us[8][164];   // raw logit row; [163] == NEGF sentinel

    int row = blockIdx.x * 8 + (threadIdx.x >> 5);   // row = t*Bn + b
    if (row >= Tn * Bn) return;
    int lane = threadIdx.x & 31;
    int w    = threadIdx.x >> 5;
    int b    = row & (Bn - 1);
    int t    = row >> 6;
    if (t >= act_lens[b]) return;                    // warp-uniform skip
    const float* p = logits + (size_t)row * Vn;

    float v[6];
    float m = NEGF;
#pragma unroll
    for (int k = 0; k < 6; k++) {
        int i = lane + 32 * k;
        v[k] = (i < Vn) ? p[i] : NEGF;
        m = fmaxf(m, v[k]);
        if (i < 164) us[w][i] = v[k];          // i==163 stays NEGF
    }
    __syncwarp();

    float blank = us[w][0];
    const int smax = 2 * label_lens[b];

    float r[NOD];
#pragma unroll
    for (int i = 0; i < NOD; i++) {
        int s  = lane * CHK + 2 * i + 1;
        int li = NOD * lane + i;               // (s-1)/2
        int ee = (s < Sn && s <= smax) ? labels[b * Ln + li] : Vn;  // Vn -> r=0
        r[i] = __expf(us[w][ee] - blank);
    }

    uint4 wd;
    wd.x = packbf(r[0], r[1]);
    wd.y = packbf(r[2], r[3]);
    wd.z = packbf(r[4], r[5]);
    wd.w = packbf(r[6], 0.f);
    g_upk[(size_t)row * 32 + lane] = wd;

    // lse reduction -> adj = lse - blank, stored [b][t]
#pragma unroll
    for (int off = 16; off; off >>= 1) m = fmaxf(m, __shfl_xor_sync(0xffffffffu, m, off));
    float sum = 0.f;
#pragma unroll
    for (int k = 0; k < 6; k++) sum += __expf(v[k] - m);
#pragma unroll
    for (int off = 16; off; off >>= 1) sum += __shfl_xor_sync(0xffffffffu, sum, off);
    if (lane == 0) g_lse[b * Tn + t] = m + __logf(sum) - blank;
}

// term aligned to kmax: keep (d==0), downshift one 64-bit unit (d==-1), else 0
__device__ __forceinline__ float termf(float m, int d) {
    return (d == 0) ? m : ((d == -1) ? m * 0x1p-64f : 0.f);
}

// ---------------------------------------------------------------------------
// Kernel 2: CTC alpha (blank-factored), one warp per batch, register-resident.
// Per step: 1 LDG.128 (imm-offset), 1 shuffle, 7 unpack ALU, 29 FMA-class.
// Exponent sync/adopt/renorm at 8-step group boundaries (branchless).
// Epilogue: warp-coalesced adj sum; last block finalizes + resets globals.
// ---------------------------------------------------------------------------
#define PREAMBLE() do {                                                        \
    int nk = __shfl_up_sync(0xffffffffu, kk, 1);                               \
    if (lane == 0) nk = kk;                                                    \
    int d = nk - kk;                                                           \
    float fo = (d <= 0) ? 1.f : ((d == 1) ? 0x1p-64f : 0.f);                   \
    _Pragma("unroll") for (int j = 0; j < CHK; j++) m[j] *= fo;                \
    kk = (d > 0) ? nk : kk;                                                    \
    int dd = (d < 0) ? d : 0;                                                  \
    sc = (dd == 0) ? 1.f : ((dd == -1) ? 0x1p-64f : 0.f);                      \
} while (0)

#define RENORM() do {                                                          \
    float mx = m[0];                                                           \
    _Pragma("unroll") for (int j = 2; j < CHK; j += 2) mx = fmaxf(mx, m[j]);   \
    int ov = (mx >= 0x1p32f) ? 1 : 0;                                          \
    float f = ov ? 0x1p-64f : 1.f;                                             \
    _Pragma("unroll") for (int j = 0; j < CHK; j++) m[j] *= f;                 \
    kk += ov;                                                                  \
} while (0)

#define BODY(Q_) do {                                                          \
    float nm = __shfl_up_sync(0xffffffffu, m[CHK - 1], 1);                     \
    if (lane == 0) nm = 0.f;                                                   \
    nm *= sc;                                                                  \
    uint4 wv = buf[Q_];                                                        \
    float r0 = __uint_as_float(wv.x << 16);                                    \
    float r1 = __uint_as_float(wv.x & 0xFFFF0000u);                            \
    float r2 = __uint_as_float(wv.y << 16);                                    \
    float r3 = __uint_as_float(wv.y & 0xFFFF0000u);                            \
    float r4 = __uint_as_float(wv.z << 16);                                    \
    float r5 = __uint_as_float(wv.z & 0xFFFF0000u);                            \
    float r6 = __uint_as_float(wv.w << 16);                                    \
    float nv[CHK];                                                             \
    nv[0]  =  m[0]  + nm;                                                      \
    nv[1]  = (m[1]  + fmaf(al[0], nm,    m[0]))  * r0;                         \
    nv[2]  =  m[2]  + m[1];                                                    \
    nv[3]  = (m[3]  + fmaf(al[1], m[1],  m[2]))  * r1;                         \
    nv[4]  =  m[4]  + m[3];                                                    \
    nv[5]  = (m[5]  + fmaf(al[2], m[3],  m[4]))  * r2;                         \
    nv[6]  =  m[6]  + m[5];                                                    \
    nv[7]  = (m[7]  + fmaf(al[3], m[5],  m[6]))  * r3;                         \
    nv[8]  =  m[8]  + m[7];                                                    \
    nv[9]  = (m[9]  + fmaf(al[4], m[7],  m[8]))  * r4;                         \
    nv[10] =  m[10] + m[9];                                                    \
    nv[11] = (m[11] + fmaf(al[5], m[9],  m[10])) * r5;                         \
    nv[12] =  m[12] + m[11];                                                   \
    nv[13] = (m[13] + fmaf(al[6], m[11], m[12])) * r6;                         \
    _Pragma("unroll") for (int j = 0; j < CHK; j++) m[j] = nv[j];              \
    buf[Q_] = __ldg(pf + (Q_) * ROWSTRIDE);                                    \
} while (0)

__global__ __launch_bounds__(32, 1) void ctc_alpha_kernel(
    const int* __restrict__ labels,
    const int* __restrict__ act_lens,
    const int* __restrict__ label_lens,
    float* __restrict__ out)
{
    const int b    = blockIdx.x;
    const int lane = threadIdx.x;
    const int act  = act_lens[b];
    const int lab  = label_lens[b];
    const int smax = 2 * lab;            // final blank state (lab >= 100)

    // skip-allowed flags for this lane's odd states
    float al[NOD];
#pragma unroll
    for (int i = 0; i < NOD; i++) {
        int s  = lane * CHK + 2 * i + 1;
        int li = NOD * lane + i;
        float af = 0.f;
        if (s >= 3 && s < Sn && s <= smax)
            af = (labels[b * Ln + li] != labels[b * Ln + li - 1]) ? 1.f : 0.f;
        al[i] = af;
    }

    // t = 0 init in blank-factored space: m[0] = 1, m[1] = r0(t=0)
    float m[CHK];
#pragma unroll
    for (int j = 0; j < CHK; j++) m[j] = 0.f;
    {
        uint4 w0 = __ldg(g_upk + (size_t)b * 32 + lane);
        if (lane == 0) { m[0] = 1.f; m[1] = __uint_as_float(w0.x << 16); }
    }
    int   kk = 0;
    float sc = 1.f;

    // prologue: slot q holds row 1+q
    uint4 buf[DP];
#pragma unroll
    for (int q = 0; q < DP; q++)
        buf[q] = __ldg(g_upk + ((size_t)(1 + q) * Bn + b) * 32 + lane);

    // group-base prefetch pointer: points at row t0 + DP
    const uint4* pf = g_upk + ((size_t)(1 + DP) * Bn + b) * 32 + lane;

    int t0 = 1;
    for (; t0 + 15 < act; t0 += 16) {    // act >= 1000 always
        PREAMBLE();
        BODY(0);  BODY(1);  BODY(2);  BODY(3);
        BODY(4);  BODY(5);  BODY(6);  BODY(7);
        RENORM();
        PREAMBLE();
        BODY(8);  BODY(9);  BODY(10); BODY(11);
        BODY(12); BODY(13); BODY(14); BODY(15);
        RENORM();
        pf += 16 * ROWSTRIDE;
    }
#pragma unroll
    for (int q = 0; q < 15; q++) {
        if (t0 + q < act) { PREAMBLE(); BODY(q); RENORM(); }
    }

    // adj sum: coalesced lane-parallel sum over g_lse[b][0..act)
    float sacc = 0.f;
    for (int t = lane; t < act; t += 32) sacc += g_lse[b * Tn + t];
#pragma unroll
    for (int o = 16; o; o >>= 1) sacc += __shfl_xor_sync(0xffffffffu, sacc, o);

    // publish final alphas and combine
    __shared__ float2 fin[32 * CHK];
#pragma unroll
    for (int j = 0; j < CHK; j++)
        fin[lane * CHK + j] = make_float2(m[j], __int_as_float(kk));
    __syncwarp();

    if (lane == 0) {
        float2 ve = fin[smax], vp2 = fin[smax - 1];
        int ke = (ve.x  > 0.f) ? __float_as_int(ve.y)  : KMIN;
        int kp = (vp2.x > 0.f) ? __float_as_int(vp2.y) : KMIN;
        int km = max(ke, kp);
        float pe = termf(ve.x, ke - km) + termf(vp2.x, kp - km);
        double ll;
        if (km == KMIN || pe <= 0.f) ll = -1e30;   // unreachable in practice
        else ll = log((double)pe) + (double)km * (64.0 * 0.6931471805599453);

        double loss_b = -ll + (double)sacc;
        atomicAdd(&g_loss_total, loss_b);
        __threadfence();
        int done = atomicAdd(&g_done, 1);
        if (done == Bn - 1) {                      // last block finalizes
            double total = atomicAdd(&g_loss_total, 0.0);   // ordered read
            int frames = 0;
#pragma unroll 8
            for (int i = 0; i < Bn; i++) frames += act_lens[i];
            out[0] = (float)(total / (double)frames);
            // reset for next graph replay (all contributors already done)
            g_loss_total = 0.0;
            g_done = 0;
        }
    }
}

// ---------------------------------------------------------------------------
extern "C" void kernel_launch(void* const* d_in, const int* in_sizes, int n_in,
                              void* d_out, int out_size)
{
    const float* logits     = (const float*)d_in[0];  // [T, B, V]
    const int*   labels     = (const int*)d_in[1];    // [B, L]
    const int*   act_lens   = (const int*)d_in[2];    // [B]
    const int*   label_lens = (const int*)d_in[3];    // [B]

    prep_kernel<<<(Tn * Bn + 7) / 8, 256>>>(logits, act_lens, labels, label_lens);
    ctc_alpha_kernel<<<Bn, 32>>>(labels, act_lens, label_lens, (float*)d_out);
}

// round 16
// speedup vs baseline: 1.3972x; 1.3972x over previous
#include <cuda_runtime.h>
#include <cuda_bf16.h>
#include <cstdint>

// Problem constants (fixed by the dataset)
#define Tn 2000
#define Bn 64
#define Vn 163
#define Ln 200
#define Sn 401          // 2*L+1 extended states
#define NEGF (-1e30f)
#define CHK 14          // states per lane (even => j parity == state parity)
#define NOD 7           // odd (label) states per lane
#define DP  16          // prefetch depth (steps)
#define KMIN (-(1 << 29))
#define ROWSTRIDE (Bn * 32)   // uint4 elements per time row

// Packed per-(t,b) row: one uint4 (8 bf16) per lane: (r0,r1)(r2,r3)(r4,r5)(r6,0)
// r_i = exp(logit[label_i] - logit[blank]); +32 pad rows => no prefetch clamp
__device__ uint4  g_upk[(Tn + 32) * Bn * 32];   // ~66.6 MB
__device__ int    g_eo[Bn * 256];      // per-b gather indices [b][i*32+lane]
__device__ float  g_adjsum[Bn * 32];   // PADDED: one 128B line per b (index b*32)
__device__ double g_loss_total;        // accumulated by alpha blocks
__device__ int    g_done;              // completion counter

// ---------------------------------------------------------------------------
// Kernel 0: per-b gather-index table (sentinel 163 -> logit NEGF -> r=0).
// Zeroes per-replay accumulators (runs first every launch/replay).
// ---------------------------------------------------------------------------
__global__ void eo_kernel(const int* __restrict__ labels,
                          const int* __restrict__ label_lens) {
    int b = blockIdx.x, lane = threadIdx.x;
    if (lane == 0) {
        g_adjsum[b * 32] = 0.f;
        if (b == 0) { g_loss_total = 0.0; g_done = 0; }
    }
    int smax = 2 * label_lens[b];
#pragma unroll
    for (int i = 0; i < NOD; i++) {
        int s  = lane * CHK + 2 * i + 1;
        int li = NOD * lane + i;               // (s-1)/2
        int ee = Vn;                           // sentinel
        if (s < Sn && s <= smax) ee = labels[b * Ln + li];
        g_eo[(b << 8) + (i << 5) + lane] = ee;
    }
}

__device__ __forceinline__ uint32_t packbf(float a, float bx) {
    __nv_bfloat162 h = __floats2bfloat162_rn(a, bx);   // x=a(lo), y=bx(hi)
    return *reinterpret_cast<uint32_t*>(&h);
}

// ---------------------------------------------------------------------------
// Kernel 1: one warp per (t,b) row (skipped when t >= act[b] — never consumed).
// Raw logits -> warp smem; emits bf16-packed r slots; accumulates
// adj = lse - logit_blank into g_adjsum[b*32].
// ---------------------------------------------------------------------------
__global__ __launch_bounds__(256) void prep_kernel(const float* __restrict__ logits,
                                                   const int* __restrict__ act_lens) {
    __shared__ float us[8][164];   // raw logit row; [163] == NEGF sentinel

    int row = blockIdx.x * 8 + (threadIdx.x >> 5);   // row = t*Bn + b
    if (row >= Tn * Bn) return;
    int lane = threadIdx.x & 31;
    int w    = threadIdx.x >> 5;
    int b    = row & (Bn - 1);
    int t    = row >> 6;
    if (t >= act_lens[b]) return;                    // warp-uniform skip
    const float* p = logits + (size_t)row * Vn;

    float v[6];
    float m = NEGF;
#pragma unroll
    for (int k = 0; k < 6; k++) {
        int i = lane + 32 * k;
        v[k] = (i < Vn) ? p[i] : NEGF;
        m = fmaxf(m, v[k]);
        if (i < 164) us[w][i] = v[k];          // i==163 stays NEGF
    }
    __syncwarp();

    float blank = us[w][0];

    float r[NOD];
#pragma unroll
    for (int i = 0; i < NOD; i++)
        r[i] = __expf(us[w][g_eo[(b << 8) + (i << 5) + lane]] - blank);

    uint4 wd;
    wd.x = packbf(r[0], r[1]);
    wd.y = packbf(r[2], r[3]);
    wd.z = packbf(r[4], r[5]);
    wd.w = packbf(r[6], 0.f);
    g_upk[(size_t)row * 32 + lane] = wd;

    // lse reduction -> adj = lse - blank; accumulate (t < act guaranteed here)
#pragma unroll
    for (int off = 16; off; off >>= 1) m = fmaxf(m, __shfl_xor_sync(0xffffffffu, m, off));
    float sum = 0.f;
#pragma unroll
    for (int k = 0; k < 6; k++) sum += __expf(v[k] - m);
#pragma unroll
    for (int off = 16; off; off >>= 1) sum += __shfl_xor_sync(0xffffffffu, sum, off);
    if (lane == 0)
        atomicAdd(&g_adjsum[b * 32], m + __logf(sum) - blank);
}

// term aligned to kmax: keep (d==0), downshift one 64-bit unit (d==-1), else 0
__device__ __forceinline__ float termf(float m, int d) {
    return (d == 0) ? m : ((d == -1) ? m * 0x1p-64f : 0.f);
}

// ---------------------------------------------------------------------------
// Kernel 2: CTC alpha (blank-factored), one warp per batch, register-resident.
// Per step: 1 LDG.128 (imm-offset), 1 shuffle, 7 unpack ALU, 29 FMA-class.
// Exponent sync/adopt/renorm at 8-step group boundaries (branchless).
// Byte-identical to the R14 measured optimum.
// ---------------------------------------------------------------------------
#define PREAMBLE() do {                                                        \
    int nk = __shfl_up_sync(0xffffffffu, kk, 1);                               \
    if (lane == 0) nk = kk;                                                    \
    int d = nk - kk;                                                           \
    float fo = (d <= 0) ? 1.f : ((d == 1) ? 0x1p-64f : 0.f);                   \
    _Pragma("unroll") for (int j = 0; j < CHK; j++) m[j] *= fo;                \
    kk = (d > 0) ? nk : kk;                                                    \
    int dd = (d < 0) ? d : 0;                                                  \
    sc = (dd == 0) ? 1.f : ((dd == -1) ? 0x1p-64f : 0.f);                      \
} while (0)

#define RENORM() do {                                                          \
    float mx = m[0];                                                           \
    _Pragma("unroll") for (int j = 2; j < CHK; j += 2) mx = fmaxf(mx, m[j]);   \
    int ov = (mx >= 0x1p32f) ? 1 : 0;                                          \
    float f = ov ? 0x1p-64f : 1.f;                                             \
    _Pragma("unroll") for (int j = 0; j < CHK; j++) m[j] *= f;                 \
    kk += ov;                                                                  \
} while (0)

#define BODY(Q_) do {                                                          \
    float nm = __shfl_up_sync(0xffffffffu, m[CHK - 1], 1);                     \
    if (lane == 0) nm = 0.f;                                                   \
    nm *= sc;                                                                  \
    uint4 wv = buf[Q_];                                                        \
    float r0 = __uint_as_float(wv.x << 16);                                    \
    float r1 = __uint_as_float(wv.x & 0xFFFF0000u);                            \
    float r2 = __uint_as_float(wv.y << 16);                                    \
    float r3 = __uint_as_float(wv.y & 0xFFFF0000u);                            \
    float r4 = __uint_as_float(wv.z << 16);                                    \
    float r5 = __uint_as_float(wv.z & 0xFFFF0000u);                            \
    float r6 = __uint_as_float(wv.w << 16);                                    \
    float nv[CHK];                                                             \
    nv[0]  =  m[0]  + nm;                                                      \
    nv[1]  = (m[1]  + fmaf(al[0], nm,    m[0]))  * r0;                         \
    nv[2]  =  m[2]  + m[1];                                                    \
    nv[3]  = (m[3]  + fmaf(al[1], m[1],  m[2]))  * r1;                         \
    nv[4]  =  m[4]  + m[3];                                                    \
    nv[5]  = (m[5]  + fmaf(al[2], m[3],  m[4]))  * r2;                         \
    nv[6]  =  m[6]  + m[5];                                                    \
    nv[7]  = (m[7]  + fmaf(al[3], m[5],  m[6]))  * r3;                         \
    nv[8]  =  m[8]  + m[7];                                                    \
    nv[9]  = (m[9]  + fmaf(al[4], m[7],  m[8]))  * r4;                         \
    nv[10] =  m[10] + m[9];                                                    \
    nv[11] = (m[11] + fmaf(al[5], m[9],  m[10])) * r5;                         \
    nv[12] =  m[12] + m[11];                                                   \
    nv[13] = (m[13] + fmaf(al[6], m[11], m[12])) * r6;                         \
    _Pragma("unroll") for (int j = 0; j < CHK; j++) m[j] = nv[j];              \
    buf[Q_] = __ldg(pf + (Q_) * ROWSTRIDE);                                    \
} while (0)

__global__ __launch_bounds__(32, 1) void ctc_alpha_kernel(
    const int* __restrict__ labels,
    const int* __restrict__ act_lens,
    const int* __restrict__ label_lens,
    float* __restrict__ out)
{
    const int b    = blockIdx.x;
    const int lane = threadIdx.x;
    const int act  = act_lens[b];
    const int lab  = label_lens[b];
    const int smax = 2 * lab;            // final blank state (lab >= 100)

    // skip-allowed flags for this lane's odd states
    float al[NOD];
#pragma unroll
    for (int i = 0; i < NOD; i++) {
        int s  = lane * CHK + 2 * i + 1;
        int li = NOD * lane + i;
        float af = 0.f;
        if (s >= 3 && s < Sn && s <= smax)
            af = (labels[b * Ln + li] != labels[b * Ln + li - 1]) ? 1.f : 0.f;
        al[i] = af;
    }

    // t = 0 init in blank-factored space: m[0] = 1, m[1] = r0(t=0)
    float m[CHK];
#pragma unroll
    for (int j = 0; j < CHK; j++) m[j] = 0.f;
    {
        uint4 w0 = __ldg(g_upk + (size_t)b * 32 + lane);
        if (lane == 0) { m[0] = 1.f; m[1] = __uint_as_float(w0.x << 16); }
    }
    int   kk = 0;
    float sc = 1.f;

    // prologue: slot q holds row 1+q
    uint4 buf[DP];
#pragma unroll
    for (int q = 0; q < DP; q++)
        buf[q] = __ldg(g_upk + ((size_t)(1 + q) * Bn + b) * 32 + lane);

    // group-base prefetch pointer: points at row t0 + DP
    const uint4* pf = g_upk + ((size_t)(1 + DP) * Bn + b) * 32 + lane;

    int t0 = 1;
    for (; t0 + 15 < act; t0 += 16) {    // act >= 1000 always
        PREAMBLE();
        BODY(0);  BODY(1);  BODY(2);  BODY(3);
        BODY(4);  BODY(5);  BODY(6);  BODY(7);
        RENORM();
        PREAMBLE();
        BODY(8);  BODY(9);  BODY(10); BODY(11);
        BODY(12); BODY(13); BODY(14); BODY(15);
        RENORM();
        pf += 16 * ROWSTRIDE;
    }
#pragma unroll
    for (int q = 0; q < 15; q++) {
        if (t0 + q < act) { PREAMBLE(); BODY(q); RENORM(); }
    }

    // publish final alphas and combine
    __shared__ float2 fin[32 * CHK];
#pragma unroll
    for (int j = 0; j < CHK; j++)
        fin[lane * CHK + j] = make_float2(m[j], __int_as_float(kk));
    __syncwarp();

    if (lane == 0) {
        float2 ve = fin[smax], vp2 = fin[smax - 1];
        int ke = (ve.x  > 0.f) ? __float_as_int(ve.y)  : KMIN;
        int kp = (vp2.x > 0.f) ? __float_as_int(vp2.y) : KMIN;
        int km = max(ke, kp);
        float pe = termf(ve.x, ke - km) + termf(vp2.x, kp - km);
        double ll;
        if (km == KMIN || pe <= 0.f) ll = -1e30;   // unreachable in practice
        else ll = log((double)pe) + (double)km * (64.0 * 0.6931471805599453);

        double loss_b = -ll + (double)g_adjsum[b * 32];
        atomicAdd(&g_loss_total, loss_b);
        __threadfence();
        int done = atomicAdd(&g_done, 1);
        if (done == Bn - 1) {                      // last block finalizes
            double total = atomicAdd(&g_loss_total, 0.0);   // ordered read
            int frames = 0;
#pragma unroll 8
            for (int i = 0; i < Bn; i++) frames += act_lens[i];
            out[0] = (float)(total / (double)frames);
        }
    }
}

// ---------------------------------------------------------------------------
extern "C" void kernel_launch(void* const* d_in, const int* in_sizes, int n_in,
                              void* d_out, int out_size)
{
    const float* logits     = (const float*)d_in[0];  // [T, B, V]
    const int*   labels     = (const int*)d_in[1];    // [B, L]
    const int*   act_lens   = (const int*)d_in[2];    // [B]
    const int*   label_lens = (const int*)d_in[3];    // [B]

    eo_kernel<<<Bn, 32>>>(labels, label_lens);
    prep_kernel<<<(Tn * Bn + 7) / 8, 256>>>(logits, act_lens);
    ctc_alpha_kernel<<<Bn, 32>>>(labels, act_lens, label_lens, (float*)d_out);
}